// round 6
// baseline (speedup 1.0000x reference)
#include <cuda_runtime.h>
#include <cuda_bf16.h>
#include <math_constants.h>

// MultiLocalCosineLinear, binned-by-pair pipeline:
//   K0 zero histogram
//   K1 top2(first_out) per row -> pair, (a,b); count hist[pair]
//   K2 exclusive scan -> bin_start, bin_cursor
//   K3 scatter row ids into bins
//   K4 one block per pair: W pair -> smem (once), stream rows warp-per-row
//   out (float32): [0,B) preds, [B,3B) logits row-major (B,2)

#define NROWS   65536
#define DDIM    768
#define NCLS    100
#define NPAIRS  4950            // 100*99/2
#define F4_PER_LANE 6           // 768/4/32

__device__ int g_hist[NPAIRS];
__device__ int g_start[NPAIRS + 1];
__device__ int g_cursor[NPAIRS];
__device__ int g_rows[NROWS];
__device__ int g_ab[NROWS];     // a | (b<<16)

__device__ __forceinline__ float warp_sum(float v) {
    #pragma unroll
    for (int o = 16; o; o >>= 1) v += __shfl_xor_sync(0xffffffffu, v, o);
    return v;
}
__device__ __forceinline__ float ldcs_f(const float* p) {
    float v; asm volatile("ld.global.cs.f32 %0, [%1];" : "=f"(v) : "l"(p)); return v;
}
__device__ __forceinline__ float4 ldcs_f4(const float4* p) {
    float4 v;
    asm volatile("ld.global.cs.v4.f32 {%0,%1,%2,%3}, [%4];"
                 : "=f"(v.x), "=f"(v.y), "=f"(v.z), "=f"(v.w) : "l"(p));
    return v;
}

// ---------------- K0: zero histogram ----------------
__global__ void k_zero() {
    int i = blockIdx.x * blockDim.x + threadIdx.x;
    if (i < NPAIRS) g_hist[i] = 0;
}

// ---------------- K1: top-2 per row + count ----------------
__global__ __launch_bounds__(256, 8)
void k_top2(const float* __restrict__ first_out) {
    const int row  = blockIdx.x * 8 + (threadIdx.x >> 5);
    const int lane = threadIdx.x & 31;
    if (row >= NROWS) return;

    const float* fo = first_out + (size_t)row * NCLS;
    float v1 = -CUDART_INF_F, v2 = -CUDART_INF_F;
    int   i1 = NCLS,          i2 = NCLS;
    #pragma unroll
    for (int t = 0; t < 4; ++t) {
        int c = lane + 32 * t;
        float v = (c < NCLS) ? ldcs_f(fo + c) : -CUDART_INF_F;
        if (v > v1) { v2 = v1; i2 = i1; v1 = v; i1 = c; }
        else if (v > v2) { v2 = v; i2 = c; }
    }
    #pragma unroll
    for (int off = 16; off; off >>= 1) {
        float w1 = __shfl_xor_sync(0xffffffffu, v1, off);
        int   j1 = __shfl_xor_sync(0xffffffffu, i1, off);
        float w2 = __shfl_xor_sync(0xffffffffu, v2, off);
        int   j2 = __shfl_xor_sync(0xffffffffu, i2, off);
        bool w1_best = (w1 > v1) || (w1 == v1 && j1 < i1);
        if (w1_best) {
            bool v1_second = (v1 > w2) || (v1 == w2 && i1 < j2);
            v2 = v1_second ? v1 : w2;
            i2 = v1_second ? i1 : j2;
            v1 = w1; i1 = j1;
        } else {
            bool w1_second = (w1 > v2) || (w1 == v2 && j1 < i2);
            if (w1_second) { v2 = w1; i2 = j1; }
        }
    }
    if (lane == 0) {
        const int a = min(i1, i2);
        const int b = max(i1, i2);
        const int pair = b * (b - 1) / 2 + a;
        g_ab[row] = a | (b << 16);
        atomicAdd(&g_hist[pair], 1);
        g_rows[row] = pair;          // temp: reuse g_rows to stash pair idx
    }
}

// ---------------- K2: exclusive scan over 4950 counts ----------------
__global__ void k_scan() {
    __shared__ int partial[1024];
    const int tid = threadIdx.x;           // 1024 threads
    const int PER = 5;                     // 1024*5 = 5120 >= NPAIRS
    int base = tid * PER;
    int loc[PER];
    int sum = 0;
    #pragma unroll
    for (int i = 0; i < PER; ++i) {
        int idx = base + i;
        int v = (idx < NPAIRS) ? g_hist[idx] : 0;
        loc[i] = sum; sum += v;
    }
    partial[tid] = sum;
    __syncthreads();
    for (int off = 1; off < 1024; off <<= 1) {
        int t = (tid >= off) ? partial[tid - off] : 0;
        __syncthreads();
        partial[tid] += t;
        __syncthreads();
    }
    int chunk_start = (tid > 0) ? partial[tid - 1] : 0;
    #pragma unroll
    for (int i = 0; i < PER; ++i) {
        int idx = base + i;
        if (idx < NPAIRS) {
            int s = chunk_start + loc[i];
            g_start[idx]  = s;
            g_cursor[idx] = s;
        }
    }
    if (tid == 1023) g_start[NPAIRS] = partial[1023];
}

// ---------------- K3: scatter rows into bins ----------------
__global__ void k_scatter() {
    int row = blockIdx.x * blockDim.x + threadIdx.x;
    if (row >= NROWS) return;
    int pair = g_rows[row];                 // stashed by K1
    int pos = atomicAdd(&g_cursor[pair], 1);
    // positions within [start, start+count) are unique; value order within a
    // bin is nondeterministic but each row's output is order-independent.
    g_rows[row] = pair;                     // keep pair (overwritten below per-pos)
    __threadfence();                        // no-op safety; pos unique anyway
    // store row id at its bin slot via a second array? single array suffices:
    // we must not clobber pair entries still being read by other threads.
    // -> use separate storage: see g_binrows below.
}

__device__ int g_binrows[NROWS];
__global__ void k_scatter2() {
    int row = blockIdx.x * blockDim.x + threadIdx.x;
    if (row >= NROWS) return;
    int pair = g_rows[row];
    int pos = atomicAdd(&g_cursor[pair], 1);
    g_binrows[pos] = row;
}

// ---------------- K4: one block per pair ----------------
__global__ __launch_bounds__(256)
void k_compute(const float* __restrict__ x,
               const float* __restrict__ weights,
               const float* __restrict__ sigma,
               float* __restrict__ out)
{
    const int pair = blockIdx.x;
    const int beg = g_start[pair];
    const int cnt = g_start[pair + 1] - beg;
    if (cnt == 0) return;

    __shared__ float sW[2 * DDIM];          // 6 KB
    __shared__ float s_scale[2];            // sigma * winv per k

    const int tid  = threadIdx.x;
    const int wid  = tid >> 5;
    const int lane = tid & 31;

    // cooperative load of both weight rows (float4)
    const float4* w4 = (const float4*)(weights + (size_t)pair * 2 * DDIM);
    float4* sw4 = (float4*)sW;
    #pragma unroll
    for (int i = tid; i < 2 * DDIM / 4; i += 256)
        sw4[i] = __ldg(w4 + i);
    __syncthreads();

    // warps 0/1 compute weight norms once
    if (wid < 2) {
        float wss = 0.f;
        const float* wr = sW + wid * DDIM;
        #pragma unroll
        for (int j = 0; j < F4_PER_LANE; ++j) {
            float4 w = ((const float4*)wr)[lane + 32 * j];
            wss = fmaf(w.x, w.x, fmaf(w.y, w.y, fmaf(w.z, w.z, fmaf(w.w, w.w, wss))));
        }
        wss = warp_sum(wss);
        if (lane == 0)
            s_scale[wid] = __ldg(sigma + pair) / fmaxf(sqrtf(wss), 1e-12f);
    }
    __syncthreads();

    const float sc0 = s_scale[0];
    const float sc1 = s_scale[1];

    for (int r = wid; r < cnt; r += 8) {
        const int row = g_binrows[beg + r];
        const int ab  = g_ab[row];
        const int a   = ab & 0xffff;
        const int b   = ab >> 16;

        const float4* x4 = (const float4*)(x + (size_t)row * DDIM);
        float xss = 0.f, d0 = 0.f, d1 = 0.f;
        #pragma unroll
        for (int j = 0; j < F4_PER_LANE; ++j) {
            float4 v = ldcs_f4(x4 + lane + 32 * j);
            float4 w0 = ((const float4*)sW)[lane + 32 * j];
            float4 w1 = ((const float4*)(sW + DDIM))[lane + 32 * j];
            xss = fmaf(v.x, v.x, fmaf(v.y, v.y, fmaf(v.z, v.z, fmaf(v.w, v.w, xss))));
            d0  = fmaf(w0.x, v.x, fmaf(w0.y, v.y, fmaf(w0.z, v.z, fmaf(w0.w, v.w, d0))));
            d1  = fmaf(w1.x, v.x, fmaf(w1.y, v.y, fmaf(w1.z, v.z, fmaf(w1.w, v.w, d1))));
        }
        xss = warp_sum(xss);
        d0  = warp_sum(d0);
        d1  = warp_sum(d1);

        if (lane == 0) {
            const float xinv = 1.0f / fmaxf(sqrtf(xss), 1e-12f);
            const float l0 = sc0 * d0 * xinv;
            const float l1 = sc1 * d1 * xinv;
            const int pred = (l1 > l0) ? b : a;     // argmax, first on tie
            out[row] = (float)pred;
            out[(size_t)NROWS + 2 * (size_t)row + 0] = l0;
            out[(size_t)NROWS + 2 * (size_t)row + 1] = l1;
        }
    }
}

extern "C" void kernel_launch(void* const* d_in, const int* in_sizes, int n_in,
                              void* d_out, int out_size) {
    const float* x        = (const float*)d_in[0];
    const float* first_o  = (const float*)d_in[1];
    const float* weights  = (const float*)d_in[2];
    const float* sigma    = (const float*)d_in[3];
    float* out = (float*)d_out;

    k_zero<<<(NPAIRS + 255) / 256, 256>>>();
    k_top2<<<NROWS / 8, 256>>>(first_o);
    k_scan<<<1, 1024>>>();
    k_scatter2<<<NROWS / 256, 256>>>();
    k_compute<<<NPAIRS, 256>>>(x, weights, sigma, out);
}